// round 17
// baseline (speedup 1.0000x reference)
#include <cuda_runtime.h>

#define B_    16
#define A_    262144
#define G_    128

// ---- prep launch: 4096 blocks x 256 thr, thread = 4 anchors of one batch
#define PTHR  256
#define PBLK  (B_ * A_ / (4 * PTHR))   /* 4096 */
#define CHUNKS_PER_B (A_ / (4 * PTHR)) /* 256 */

// ---- main launch: 1024 blocks x 256 thr, thread = 1 anchor (R8 proven)
#define NTHR  256
#define NBLK  (A_ / NTHR)              /* 1024 */
#define NWARP (NTHR / 32)              /* 8 */

// Pre-transformed gt table: {gcx, gcy, log(gw), log(gh)} per (b, g).
__device__ float4   g_gt[B_ * G_];
// Per-batch fg counts (int atomics -> deterministic) and weights 1/max(1,n).
__device__ int      g_cnt[B_];
__device__ float    g_w[B_];
// Per-block weighted partials.
__device__ float    g_bpart[NBLK];
__device__ unsigned g_done1 = 0;
__device__ unsigned g_done2 = 0;

// ---------------------------------------------------------------------------
// K1 (lean count-only): block = (batch, chunk). ONE int4 load per thread
// (4 anchors), warp shfl count, one atomicAdd per block. NO shadow store
// (the int8 shadow was a consistent ~6us bench loss across R12/R14/R15).
// Also pre-transforms gt (first 2048 gids).
// ---------------------------------------------------------------------------
__global__ void __launch_bounds__(PTHR)
prep_kernel(const float4* __restrict__ gt, const int* __restrict__ midx)
{
    __shared__ int s_c[PTHR / 32];
    __shared__ unsigned s_t;

    const int tid  = threadIdx.x;
    const int lane = tid & 31;
    const int warp = tid >> 5;

    const int gid = blockIdx.x * PTHR + tid;
    if (gid < B_ * G_) {
        float4 g = gt[gid];
        float gw = g.z - g.x;
        float gh = g.w - g.y;
        g_gt[gid] = make_float4(g.x + 0.5f * gw, g.y + 0.5f * gh,
                                __logf(gw), __logf(gh));
    }

    const int b     = blockIdx.x >> 8;          // / CHUNKS_PER_B
    const int chunk = blockIdx.x & (CHUNKS_PER_B - 1);
    const int idx   = b * A_ + chunk * (4 * PTHR) + tid * 4;

    int4 mv = __ldcs(reinterpret_cast<const int4*>(&midx[idx]));  // 16B load

    int c = (mv.x >= 0) + (mv.y >= 0) + (mv.z >= 0) + (mv.w >= 0);
#pragma unroll
    for (int o = 16; o > 0; o >>= 1)
        c += __shfl_down_sync(0xffffffffu, c, o);
    if (lane == 0) s_c[warp] = c;
    __syncthreads();

    if (tid == 0) {
        int tot = 0;
#pragma unroll
        for (int w = 0; w < PTHR / 32; w++) tot += s_c[w];
        atomicAdd(&g_cnt[b], tot);          // 4096 atomics total, 256/addr
        __threadfence();
        s_t = atomicAdd(&g_done1, 1u);
    }
    __syncthreads();

    if (s_t == (unsigned)(PBLK - 1)) {
        if (tid < B_) {
            int cc = g_cnt[tid];
            g_w[tid]   = 1.0f / (float)(cc > 1 ? cc : 1);
            g_cnt[tid] = 0;                 // reset for next graph replay
        }
        if (tid == 0) g_done1 = 0;
    }
}

// ---------------------------------------------------------------------------
// K2: EXACT R8 main (proven best bench: 23.0us total) + smem weight
// broadcast (the only verified-harmless tweak). Reads midx int32 directly.
// ---------------------------------------------------------------------------
__global__ void __launch_bounds__(NTHR, 7)
retina_loss_main(const float4* __restrict__ bbox,     // [B, A, 4]
                 const float4* __restrict__ anchors,  // [A, 4]
                 const int*    __restrict__ midx,     // [B, A]
                 float*        __restrict__ out)
{
    __shared__ float s_w[B_];
    __shared__ float s_sum[NWARP];
    __shared__ unsigned s_t;

    const int tid  = threadIdx.x;
    const int lane = tid & 31;
    const int warp = tid >> 5;
    const int a    = blockIdx.x * NTHR + tid;   // NBLK*NTHR == A_

    if (tid < B_) s_w[tid] = g_w[tid];

    // Anchor loaded ONCE, reused for all 16 batches.
    float4 an = __ldcs(&anchors[a]);
    float ex_w  = an.z - an.x;
    float ex_h  = an.w - an.y;
    float ex_cx = an.x + 0.5f * ex_w;
    float ex_cy = an.y + 0.5f * ex_h;
    float iw   = 1.0f / ex_w;
    float ih   = 1.0f / ex_h;
    float lexw = __logf(ex_w);
    float lexh = __logf(ex_h);

    // Front-batch all 16 matched-index loads (MLP).
    int m[B_];
#pragma unroll
    for (int b = 0; b < B_; b++)
        m[b] = __ldcs(&midx[(size_t)b * A_ + a]);

    __syncthreads();   // s_w ready

    float s0 = 0.0f, s1 = 0.0f, s2 = 0.0f, s3 = 0.0f;

#pragma unroll
    for (int b = 0; b < B_; b++) {
        const bool fg = (m[b] >= 0);
        float4 r = __ldcs(&bbox[(size_t)b * A_ + a]);
        float4 t = g_gt[b * G_ + (fg ? m[b] : 0)];  // 32 KB table, L1-resident

        float dx = (t.x - ex_cx) * iw;
        float dy = (t.y - ex_cy) * ih;
        float dw = t.z - lexw;     // log(gw) - log(ex_w)
        float dh = t.w - lexh;

        float l1 = fabsf(r.x - dx) + fabsf(r.y - dy)
                 + fabsf(r.z - dw) + fabsf(r.w - dh);
        float c  = fg ? s_w[b] * l1 : 0.0f;

        // 4 rotating accumulators: dependency chain length B_/4.
        if      ((b & 3) == 0) s0 += c;
        else if ((b & 3) == 1) s1 += c;
        else if ((b & 3) == 2) s2 += c;
        else                   s3 += c;
    }

    float s = (s0 + s1) + (s2 + s3);

    // ONE warp reduce for the whole thread.
#pragma unroll
    for (int o = 16; o > 0; o >>= 1)
        s += __shfl_down_sync(0xffffffffu, s, o);
    if (lane == 0) s_sum[warp] = s;
    __syncthreads();

    if (tid == 0) {
        float bs = 0.0f;
#pragma unroll
        for (int w = 0; w < NWARP; w++) bs += s_sum[w];
        g_bpart[blockIdx.x] = bs;
    }

    // ---- last-block final fold (fixed order -> deterministic) ----
    __threadfence();
    __syncthreads();
    if (tid == 0) s_t = atomicAdd(&g_done2, 1u);
    __syncthreads();

    if (s_t == (unsigned)(NBLK - 1)) {
        float v = 0.0f;
#pragma unroll
        for (int i = 0; i < NBLK / NTHR; i++)     // 4 per thread
            v += __ldcg(&g_bpart[tid + i * NTHR]);
#pragma unroll
        for (int o = 16; o > 0; o >>= 1)
            v += __shfl_down_sync(0xffffffffu, v, o);
        if (lane == 0) s_sum[warp] = v;
        __syncthreads();
        if (tid == 0) {
            float tot = 0.0f;
#pragma unroll
            for (int w = 0; w < NWARP; w++) tot += s_sum[w];
            *out = tot * (1.0f / (float)B_);
            g_done2 = 0;
        }
    }
}

extern "C" void kernel_launch(void* const* d_in, const int* in_sizes, int n_in,
                              void* d_out, int out_size)
{
    const float4* bbox    = (const float4*)d_in[0];  // bbox_regression [B, A, 4] f32
    const float4* anchors = (const float4*)d_in[1];  // anchors [A, 4] f32
    const float4* gt      = (const float4*)d_in[2];  // gt_boxes [B, G, 4] f32
    const int*    midx    = (const int*)d_in[3];     // matched_idxs [B, A] i32

    prep_kernel<<<PBLK, PTHR>>>(gt, midx);
    retina_loss_main<<<NBLK, NTHR>>>(bbox, anchors, midx, (float*)d_out);
}